// round 16
// baseline (speedup 1.0000x reference)
#include <cuda_runtime.h>
#include <cuda_bf16.h>
#include <cstdint>

static constexpr int Sc = 2048, Dc = 64;

// fragment buffers:
// Q: ((bh*128+blk)*2+sp)*4+ks -> [lane] uint4(a0,a1,a2,a3)
// K: ((bh*256+cbg)*2+sp)*2+kp -> [lane] uint4(ks_even b0,b1, ks_odd b0,b1)
__device__ uint4 g_qfrag[64 * 128 * 2 * 4 * 32];
__device__ uint4 g_kfrag[64 * 256 * 2 * 2 * 32];
// gate table: [bh][qb16 (128)][kb (256)][16 rows] u8  (33.5 MB, uint4-aligned)
__device__ uint4 g_gate4[64 * 128 * 256];
// hi-only per-row maxima
__device__ float g_rowmax[64 * 2048];

__device__ __forceinline__ void threefry2x32(uint32_t c0, uint32_t c1,
                                             uint32_t& o0, uint32_t& o1)
{
    const uint32_t K0 = 0u, K1 = 42u, K2 = 0x1BD11BDAu ^ K0 ^ K1;
    uint32_t x0 = c0 + K0, x1 = c1 + K1;
#define TF_R(r) { x0 += x1; x1 = __funnelshift_l(x1, x1, (r)); x1 ^= x0; }
    TF_R(13) TF_R(15) TF_R(26) TF_R(6)  x0 += K1; x1 += K2 + 1u;
    TF_R(17) TF_R(29) TF_R(16) TF_R(24) x0 += K2; x1 += K0 + 2u;
    TF_R(13) TF_R(15) TF_R(26) TF_R(6)  x0 += K0; x1 += K1 + 3u;
    TF_R(17) TF_R(29) TF_R(16) TF_R(24) x0 += K1; x1 += K2 + 4u;
    TF_R(13) TF_R(15) TF_R(26) TF_R(6)  x0 += K2; x1 += K0 + 5u;
#undef TF_R
    o0 = x0; o1 = x1;
}
__device__ __forceinline__ bool keep_mask(uint32_t bh, uint32_t gq, uint32_t gk)
{
    uint32_t i = (bh << 22) | (gq << 11) | gk, b0, b1;
    threefry2x32(0u, i, b0, b1);
    return ((b0 ^ b1) >> 9) < 838861u;
}

__device__ __forceinline__ uint32_t pk_bf16(float lo, float hi)
{ uint32_t r; asm("cvt.rn.bf16x2.f32 %0, %1, %2;" : "=r"(r) : "f"(hi), "f"(lo)); return r; }

__device__ __forceinline__ uint32_t pk_split(float x, float y, int sp)
{
    float xh = __bfloat162float(__float2bfloat16(x));
    float yh = __bfloat162float(__float2bfloat16(y));
    return sp ? pk_bf16(x - xh, y - yh) : pk_bf16(xh, yh);
}

__device__ __forceinline__ void mma16816(float& c0, float& c1, float& c2, float& c3,
                                         uint32_t a0, uint32_t a1, uint32_t a2, uint32_t a3,
                                         uint32_t b0, uint32_t b1)
{
    asm volatile("mma.sync.aligned.m16n8k16.row.col.f32.bf16.bf16.f32 "
                 "{%0,%1,%2,%3}, {%4,%5,%6,%7}, {%8,%9}, {%0,%1,%2,%3};"
                 : "+f"(c0), "+f"(c1), "+f"(c2), "+f"(c3)
                 : "r"(a0), "r"(a1), "r"(a2), "r"(a3), "r"(b0), "r"(b1));
}

// ---------------- pre-pass (unchanged) ---------------------------------------
__global__ void __launch_bounds__(256)
prepass_kernel(const float* __restrict__ q, const float* __restrict__ k)
{
    int gw = (blockIdx.x * 256 + threadIdx.x) >> 5;
    int lane = threadIdx.x & 31;
    if (gw < 64 * 128 * 2 * 4) {
        int ks = gw & 3, sp = (gw >> 2) & 1, blk = (gw >> 3) & 127, bh = gw >> 10;
        int r0 = blk * 16 + (lane >> 2);
        int kb = ks * 16 + (lane & 3) * 2;
        const float* qb = q + ((size_t)bh * Sc) * Dc;
        float2 p00 = *(const float2*)(qb + (size_t)r0 * Dc + kb);
        float2 p10 = *(const float2*)(qb + (size_t)(r0 + 8) * Dc + kb);
        float2 p01 = *(const float2*)(qb + (size_t)r0 * Dc + kb + 8);
        float2 p11 = *(const float2*)(qb + (size_t)(r0 + 8) * Dc + kb + 8);
        uint4 o;
        o.x = pk_split(p00.x * 8.f, p00.y * 8.f, sp);
        o.y = pk_split(p10.x * 8.f, p10.y * 8.f, sp);
        o.z = pk_split(p01.x * 8.f, p01.y * 8.f, sp);
        o.w = pk_split(p11.x * 8.f, p11.y * 8.f, sp);
        g_qfrag[(size_t)gw * 32 + lane] = o;
    } else {
        int w2 = gw - 64 * 128 * 2 * 4;
        int kp = w2 & 1, sp = (w2 >> 1) & 1, cbg = (w2 >> 2) & 255, bh = w2 >> 10;
        int n = cbg * 8 + (lane >> 2);
        const float* kr = k + ((size_t)bh * Sc + n) * Dc;
        uint4 o;
        int k0 = (kp * 2) * 16 + (lane & 3) * 2;
        o.x = pk_split(kr[k0], kr[k0 + 1], sp);
        o.y = pk_split(kr[k0 + 8], kr[k0 + 9], sp);
        int k1 = (kp * 2 + 1) * 16 + (lane & 3) * 2;
        o.z = pk_split(kr[k1], kr[k1 + 1], sp);
        o.w = pk_split(kr[k1 + 8], kr[k1 + 9], sp);
        g_kfrag[(size_t)w2 * 32 + lane] = o;
    }
}

// ======== KERNEL A: dense hi-only sweep -> row maxima + gate table ==========
__global__ void __launch_bounds__(128, 5)
pass1_kernel(int dummy)
{
    __shared__ uint4 sKH[1024];          // 16 KB: hi-only K tile
    __shared__ uint8_t sRB[4 * 4096];    // 16 KB: per-warp gate staging

    const int tid = threadIdx.x, w = tid >> 5, lane = tid & 31;
    const uint32_t bh = blockIdx.y;
    const int blk = blockIdx.x * 4 + w;   // q16-block index (0..127)
    const uint4* kfb = g_kfrag + (size_t)bh * 32768;

    uint4 AH[4];
    {
        const uint4* qf = g_qfrag + ((size_t)(bh * 128 + blk) * 2) * 4 * 32;
#pragma unroll
        for (int ks = 0; ks < 4; ++ks) AH[ks] = qf[ks * 32 + lane];
    }

    float mx0 = -1e30f, mx1 = -1e30f;
    for (int kt = 0; kt < 16; ++kt) {
        __syncthreads();
#pragma unroll
        for (int i = 0; i < 8; ++i) {
            int li = tid + i * 128;
            sKH[li] = kfb[kt * 2048 + ((li >> 6) * 128) + (li & 63)];
        }
        __syncthreads();

#pragma unroll 2
        for (int cb = 0; cb < 16; ++cb) {
            uint4 Bh0 = sKH[cb * 64 + lane];
            uint4 Bh1 = sKH[cb * 64 + 32 + lane];
            float h0 = 0.f, h1 = 0.f, h2 = 0.f, h3 = 0.f;
            mma16816(h0, h1, h2, h3, AH[0].x, AH[0].y, AH[0].z, AH[0].w, Bh0.x, Bh0.y);
            mma16816(h0, h1, h2, h3, AH[1].x, AH[1].y, AH[1].z, AH[1].w, Bh0.z, Bh0.w);
            mma16816(h0, h1, h2, h3, AH[2].x, AH[2].y, AH[2].z, AH[2].w, Bh1.x, Bh1.y);
            mma16816(h0, h1, h2, h3, AH[3].x, AH[3].y, AH[3].z, AH[3].w, Bh1.z, Bh1.w);
            float t0 = fmaxf(h0, h1), t1 = fmaxf(h2, h3);
            mx0 = fmaxf(mx0, t0);
            mx1 = fmaxf(mx1, t1);
            t0 = fmaxf(t0, __shfl_xor_sync(0xffffffffu, t0, 1));
            t0 = fmaxf(t0, __shfl_xor_sync(0xffffffffu, t0, 2));
            t1 = fmaxf(t1, __shfl_xor_sync(0xffffffffu, t1, 1));
            t1 = fmaxf(t1, __shfl_xor_sync(0xffffffffu, t1, 2));
            if ((lane & 3) == 0) {
                int r = lane >> 2;
                int base = (w * 256 + kt * 16 + cb) * 16;
                int b0 = min(max((int)ceilf(t0) - 100, 0), 255);
                int b1 = min(max((int)ceilf(t1) - 100, 0), 255);
                sRB[base + r] = (uint8_t)b0;
                sRB[base + r + 8] = (uint8_t)b1;
            }
        }
    }

    // row maxima -> global
    mx0 = fmaxf(mx0, __shfl_xor_sync(0xffffffffu, mx0, 1));
    mx0 = fmaxf(mx0, __shfl_xor_sync(0xffffffffu, mx0, 2));
    mx1 = fmaxf(mx1, __shfl_xor_sync(0xffffffffu, mx1, 1));
    mx1 = fmaxf(mx1, __shfl_xor_sync(0xffffffffu, mx1, 2));
    if ((lane & 3) == 0) {
        int r = lane >> 2;
        g_rowmax[bh * 2048 + blk * 16 + r] = mx0;
        g_rowmax[bh * 2048 + blk * 16 + r + 8] = mx1;
    }
    __syncwarp();

    // dump gate slab (4 KB per warp, coalesced)
    {
        const uint4* src = (const uint4*)sRB + w * 256;
        uint4* dst = g_gate4 + ((size_t)(bh * 128 + blk)) * 256;
#pragma unroll
        for (int i = 0; i < 8; ++i)
            dst[lane + 32 * i] = src[lane + 32 * i];
    }
    (void)dummy;
}

// ======== KERNEL B: sparse gated pass 2 ======================================
__global__ void __launch_bounds__(256, 2)
pass2_kernel(const float* __restrict__ gv, float* __restrict__ gout)
{
    __shared__ uint4 sAL[8 * 4 * 32];    // 16 KB: A_lo frags per warp
    __shared__ uint8_t sTH[8 * 16];      // per-warp per-row threshold bytes

    const int tid = threadIdx.x, w = tid >> 5, lane = tid & 31;
    const uint32_t bh = blockIdx.y;
    const int q0 = blockIdx.x * 128;
    const int blk = blockIdx.x * 8 + w;
    const uint4* kfb = g_kfrag + (size_t)bh * 32768;
    const uint8_t* gate = (const uint8_t*)(g_gate4 + ((size_t)(bh * 128 + blk)) * 256);

    uint4 AH[4];
    {
        const uint4* qf = g_qfrag + ((size_t)(bh * 128 + blk) * 2) * 4 * 32;
#pragma unroll
        for (int ks = 0; ks < 4; ++ks) AH[ks] = qf[ks * 32 + lane];
#pragma unroll
        for (int ks = 0; ks < 4; ++ks)
            sAL[(w * 4 + ks) * 32 + lane] = qf[(4 + ks) * 32 + lane];
    }

    // fixed exp bases from pass-1 row maxima
    const uint32_t gq0 = (uint32_t)(q0 + w * 16 + (lane >> 2));
    const float m0 = g_rowmax[bh * 2048 + gq0];
    const float m1 = g_rowmax[bh * 2048 + gq0 + 8];
    if ((lane & 3) == 0) {
        int r = lane >> 2;
        sTH[w * 16 + r]     = (uint8_t)min(max((int)floorf(m0 - 31.f) - 100, 0), 255);
        sTH[w * 16 + r + 8] = (uint8_t)min(max((int)floorf(m1 - 31.f) - 100, 0), 255);
    }
    __syncwarp();
    const uint2 thv = *(const uint2*)&sTH[w * 16 + (lane >> 4) * 8];
    const int cb_l = lane & 15;

    float O[2][16];
#pragma unroll
    for (int r = 0; r < 2; ++r)
#pragma unroll
        for (int c = 0; c < 16; ++c) O[r][c] = 0.f;
    float l0 = 0.f, l1 = 0.f;
    const float* vb = gv + (size_t)bh * Sc * Dc;

    for (int kt = 0; kt < 16; ++kt) {
        // union-of-rows gate from global table
        uint2 rbv = *(const uint2*)&gate[(kt * 16 + cb_l) * 16 + (lane >> 4) * 8];
        unsigned ge = __vsetgeu4(rbv.x, thv.x) | __vsetgeu4(rbv.y, thv.y);
        unsigned bal = __ballot_sync(0xffffffffu, ge != 0u);
        unsigned bmask = (bal & 0xffffu) | (bal >> 16);

        while (bmask) {
            const int cb = __ffs(bmask) - 1;
            bmask &= bmask - 1;

            const uint4* kb = kfb + (size_t)(kt * 16 + cb) * 128;
            uint4 Bh0 = kb[lane];
            uint4 Bh1 = kb[32 + lane];
            uint4 Bl0 = kb[64 + lane];
            uint4 Bl1 = kb[96 + lane];

            float h0 = 0.f, h1 = 0.f, h2 = 0.f, h3 = 0.f;
            float x0 = 0.f, x1 = 0.f, x2 = 0.f, x3 = 0.f;
#pragma unroll
            for (int ks = 0; ks < 4; ++ks) {
                uint4 AL = sAL[(w * 4 + ks) * 32 + lane];
                uint32_t hb0 = (ks & 1) ? ((ks >> 1) ? Bh1.z : Bh0.z)
                                        : ((ks >> 1) ? Bh1.x : Bh0.x);
                uint32_t hb1 = (ks & 1) ? ((ks >> 1) ? Bh1.w : Bh0.w)
                                        : ((ks >> 1) ? Bh1.y : Bh0.y);
                uint32_t lb0 = (ks & 1) ? ((ks >> 1) ? Bl1.z : Bl0.z)
                                        : ((ks >> 1) ? Bl1.x : Bl0.x);
                uint32_t lb1 = (ks & 1) ? ((ks >> 1) ? Bl1.w : Bl0.w)
                                        : ((ks >> 1) ? Bl1.y : Bl0.y);
                mma16816(x0, x1, x2, x3, AL.x, AL.y, AL.z, AL.w, hb0, hb1);
                mma16816(h0, h1, h2, h3, AH[ks].x, AH[ks].y, AH[ks].z, AH[ks].w, hb0, hb1);
                mma16816(x0, x1, x2, x3, AH[ks].x, AH[ks].y, AH[ks].z, AH[ks].w, lb0, lb1);
            }
            float c0 = h0 + x0, c1 = h1 + x1, c2 = h2 + x2, c3 = h3 + x3;

            float e0 = (c0 > m0 - 28.f) ? __expf(c0 - m0) : 0.f;
            float e1 = (c1 > m0 - 28.f) ? __expf(c1 - m0) : 0.f;
            float e2 = (c2 > m1 - 28.f) ? __expf(c2 - m1) : 0.f;
            float e3 = (c3 > m1 - 28.f) ? __expf(c3 - m1) : 0.f;
            l0 += e0 + e1;
            l1 += e2 + e3;

            const int gk0 = kt * 128 + cb * 8 + (lane & 3) * 2;
            bool sv[4] = {false, false, false, false};
            float p10[4] = {0.f, 0.f, 0.f, 0.f};
            if (e0 > 0.f && keep_mask(bh, gq0, gk0))         { sv[0] = true; p10[0] = e0 * 10.f; }
            if (e1 > 0.f && keep_mask(bh, gq0, gk0 + 1))     { sv[1] = true; p10[1] = e1 * 10.f; }
            if (e2 > 0.f && keep_mask(bh, gq0 + 8, gk0))     { sv[2] = true; p10[2] = e2 * 10.f; }
            if (e3 > 0.f && keep_mask(bh, gq0 + 8, gk0 + 1)) { sv[3] = true; p10[3] = e3 * 10.f; }

            if (__ballot_sync(0xffffffffu, sv[0] | sv[1] | sv[2] | sv[3])) {
#pragma unroll
                for (int pos = 0; pos < 4; ++pos) {
                    unsigned mk = __ballot_sync(0xffffffffu, sv[pos]);
                    while (mk) {
                        int src = __ffs(mk) - 1;
                        mk &= mk - 1;
                        int gkb  = __shfl_sync(0xffffffffu, gk0 + (pos & 1), src);
                        float pb = __shfl_sync(0xffffffffu, p10[pos], src);
                        if ((lane >> 2) == (src >> 2)) {
                            const float* vc = vb + (size_t)gkb * Dc + (lane & 3) * 16;
                            float* Or = O[pos >> 1];
#pragma unroll
                            for (int c = 0; c < 4; ++c) {
                                float4 vv = *(const float4*)(vc + 4 * c);
                                Or[4 * c + 0] = fmaf(pb, vv.x, Or[4 * c + 0]);
                                Or[4 * c + 1] = fmaf(pb, vv.y, Or[4 * c + 1]);
                                Or[4 * c + 2] = fmaf(pb, vv.z, Or[4 * c + 2]);
                                Or[4 * c + 3] = fmaf(pb, vv.w, Or[4 * c + 3]);
                            }
                        }
                    }
                }
            }
        }
    }

    // epilogue
    l0 += __shfl_xor_sync(0xffffffffu, l0, 1);
    l0 += __shfl_xor_sync(0xffffffffu, l0, 2);
    l1 += __shfl_xor_sync(0xffffffffu, l1, 1);
    l1 += __shfl_xor_sync(0xffffffffu, l1, 2);
    float il0 = 1.0f / l0, il1 = 1.0f / l1;

    const int gr0 = q0 + w * 16 + (lane >> 2);
    float* o0 = gout + ((size_t)bh * Sc + gr0) * Dc + (lane & 3) * 16;
    float* o1 = gout + ((size_t)bh * Sc + gr0 + 8) * Dc + (lane & 3) * 16;
#pragma unroll
    for (int c = 0; c < 4; ++c) {
        *(float4*)(o0 + 4 * c) = make_float4(O[0][4*c] * il0, O[0][4*c+1] * il0,
                                             O[0][4*c+2] * il0, O[0][4*c+3] * il0);
        *(float4*)(o1 + 4 * c) = make_float4(O[1][4*c] * il1, O[1][4*c+1] * il1,
                                             O[1][4*c+2] * il1, O[1][4*c+3] * il1);
    }
}

extern "C" void kernel_launch(void* const* d_in, const int* in_sizes, int n_in,
                              void* d_out, int out_size)
{
    (void)in_sizes; (void)n_in; (void)out_size;
    const float* q = (const float*)d_in[0];
    const float* k = (const float*)d_in[1];
    const float* v = (const float*)d_in[2];
    float* o = (float*)d_out;

    prepass_kernel<<<16384, 256>>>(q, k);

    dim3 gridA(32, 64);
    pass1_kernel<<<gridA, 128>>>(0);

    dim3 gridB(Sc / 128, 64);
    pass2_kernel<<<gridB, 256>>>(v, o);
}

// round 17
// speedup vs baseline: 1.3283x; 1.3283x over previous
#include <cuda_runtime.h>
#include <cuda_bf16.h>
#include <cstdint>

static constexpr int Sc = 2048, Dc = 64;

// hi-only fragment buffers:
// Q: ((bh*128+blk)*4+ks)*32+lane -> uint4(a0,a1,a2,a3)
// K: ((bh*256+cbg)*2+kp)*32+lane -> uint4(ks_even b0,b1, ks_odd b0,b1)
__device__ uint4 g_qfrag[64 * 128 * 4 * 32];
__device__ uint4 g_kfrag[64 * 256 * 2 * 32];
// gate bytes: per (bh, qblk16): 256 kblocks x 16 rows x 4 colpairs = 16 KB
__device__ uint4 g_gate[64 * 128 * 1024];     // 134 MB
__device__ float g_rowmax[64 * 2048];

__device__ __forceinline__ void threefry2x32(uint32_t c0, uint32_t c1,
                                             uint32_t& o0, uint32_t& o1)
{
    const uint32_t K0 = 0u, K1 = 42u, K2 = 0x1BD11BDAu ^ K0 ^ K1;
    uint32_t x0 = c0 + K0, x1 = c1 + K1;
#define TF_R(r) { x0 += x1; x1 = __funnelshift_l(x1, x1, (r)); x1 ^= x0; }
    TF_R(13) TF_R(15) TF_R(26) TF_R(6)  x0 += K1; x1 += K2 + 1u;
    TF_R(17) TF_R(29) TF_R(16) TF_R(24) x0 += K2; x1 += K0 + 2u;
    TF_R(13) TF_R(15) TF_R(26) TF_R(6)  x0 += K0; x1 += K1 + 3u;
    TF_R(17) TF_R(29) TF_R(16) TF_R(24) x0 += K1; x1 += K2 + 4u;
    TF_R(13) TF_R(15) TF_R(26) TF_R(6)  x0 += K2; x1 += K0 + 5u;
#undef TF_R
    o0 = x0; o1 = x1;
}
__device__ __forceinline__ bool keep_mask(uint32_t bh, uint32_t gq, uint32_t gk)
{
    uint32_t i = (bh << 22) | (gq << 11) | gk, b0, b1;
    threefry2x32(0u, i, b0, b1);
    return ((b0 ^ b1) >> 9) < 838861u;
}

__device__ __forceinline__ uint32_t pk_bf16(float lo, float hi)
{ uint32_t r; asm("cvt.rn.bf16x2.f32 %0, %1, %2;" : "=r"(r) : "f"(hi), "f"(lo)); return r; }

__device__ __forceinline__ void mma16816(float& c0, float& c1, float& c2, float& c3,
                                         uint32_t a0, uint32_t a1, uint32_t a2, uint32_t a3,
                                         uint32_t b0, uint32_t b1)
{
    asm volatile("mma.sync.aligned.m16n8k16.row.col.f32.bf16.bf16.f32 "
                 "{%0,%1,%2,%3}, {%4,%5,%6,%7}, {%8,%9}, {%0,%1,%2,%3};"
                 : "+f"(c0), "+f"(c1), "+f"(c2), "+f"(c3)
                 : "r"(a0), "r"(a1), "r"(a2), "r"(a3), "r"(b0), "r"(b1));
}

// ---------------- pre-pass: hi-only fragments --------------------------------
__global__ void __launch_bounds__(256)
prepass_kernel(const float* __restrict__ q, const float* __restrict__ k)
{
    int gw = (blockIdx.x * 256 + threadIdx.x) >> 5;
    int lane = threadIdx.x & 31;
    if (gw < 64 * 128 * 4) {
        int ks = gw & 3, blk = (gw >> 2) & 127, bh = gw >> 9;
        int r0 = blk * 16 + (lane >> 2);
        int kb = ks * 16 + (lane & 3) * 2;
        const float* qb = q + ((size_t)bh * Sc) * Dc;
        float2 p00 = *(const float2*)(qb + (size_t)r0 * Dc + kb);
        float2 p10 = *(const float2*)(qb + (size_t)(r0 + 8) * Dc + kb);
        float2 p01 = *(const float2*)(qb + (size_t)r0 * Dc + kb + 8);
        float2 p11 = *(const float2*)(qb + (size_t)(r0 + 8) * Dc + kb + 8);
        uint4 o;
        o.x = pk_bf16(p00.x * 8.f, p00.y * 8.f);
        o.y = pk_bf16(p10.x * 8.f, p10.y * 8.f);
        o.z = pk_bf16(p01.x * 8.f, p01.y * 8.f);
        o.w = pk_bf16(p11.x * 8.f, p11.y * 8.f);
        g_qfrag[(size_t)gw * 32 + lane] = o;
    } else {
        int w2 = gw - 64 * 128 * 4;
        int kp = w2 & 1, cbg = (w2 >> 1) & 255, bh = w2 >> 9;
        int n = cbg * 8 + (lane >> 2);
        const float* kr = k + ((size_t)bh * Sc + n) * Dc;
        uint4 o;
        int k0 = (kp * 2) * 16 + (lane & 3) * 2;
        o.x = pk_bf16(kr[k0], kr[k0 + 1]);
        o.y = pk_bf16(kr[k0 + 8], kr[k0 + 9]);
        int k1 = (kp * 2 + 1) * 16 + (lane & 3) * 2;
        o.z = pk_bf16(kr[k1], kr[k1 + 1]);
        o.w = pk_bf16(kr[k1 + 8], kr[k1 + 9]);
        g_kfrag[(size_t)w2 * 32 + lane] = o;
    }
}

// ======== KERNEL A: dense hi sweep -> row maxima + per-element gate bytes ===
__global__ void __launch_bounds__(128, 5)
pass1_kernel(int dummy)
{
    __shared__ uint4 sKH[1024];        // 16 KB: hi K tile for current kt
    __shared__ uint4 sGB4[4 * 64];     //  4 KB: per-warp gate staging (1 KB)
    uint8_t* sGB = (uint8_t*)sGB4;

    const int tid = threadIdx.x, w = tid >> 5, lane = tid & 31;
    const uint32_t bh = blockIdx.y;
    const int blk = blockIdx.x * 4 + w;
    const uint4* kfb = g_kfrag + (size_t)bh * 16384;

    uint4 AH[4];
    {
        const uint4* qf = g_qfrag + (size_t)(bh * 128 + blk) * 4 * 32;
#pragma unroll
        for (int ks = 0; ks < 4; ++ks) AH[ks] = qf[ks * 32 + lane];
    }

    float mx0 = -1e30f, mx1 = -1e30f;
    for (int kt = 0; kt < 16; ++kt) {
        __syncthreads();
#pragma unroll
        for (int i = 0; i < 8; ++i)
            sKH[tid + i * 128] = kfb[kt * 1024 + tid + i * 128];
        __syncthreads();

#pragma unroll 2
        for (int cb = 0; cb < 16; ++cb) {
            uint4 Bh0 = sKH[cb * 64 + lane];
            uint4 Bh1 = sKH[cb * 64 + 32 + lane];
            float a0 = 0.f, a1 = 0.f, a2 = 0.f, a3 = 0.f;
            float b0 = 0.f, b1 = 0.f, b2 = 0.f, b3 = 0.f;
            mma16816(a0, a1, a2, a3, AH[0].x, AH[0].y, AH[0].z, AH[0].w, Bh0.x, Bh0.y);
            mma16816(b0, b1, b2, b3, AH[2].x, AH[2].y, AH[2].z, AH[2].w, Bh1.x, Bh1.y);
            mma16816(a0, a1, a2, a3, AH[1].x, AH[1].y, AH[1].z, AH[1].w, Bh0.z, Bh0.w);
            mma16816(b0, b1, b2, b3, AH[3].x, AH[3].y, AH[3].z, AH[3].w, Bh1.z, Bh1.w);
            float t0 = fmaxf(a0 + b0, a1 + b1);
            float t1 = fmaxf(a2 + b2, a3 + b3);
            mx0 = fmaxf(mx0, t0);
            mx1 = fmaxf(mx1, t1);
            int v0 = min(max(__float2int_ru(t0) - 100, 0), 255);
            int v1 = min(max(__float2int_ru(t1) - 100, 0), 255);
            sGB[w * 1024 + cb * 64 + lane] = (uint8_t)v0;       // rows 0..7
            sGB[w * 1024 + cb * 64 + 32 + lane] = (uint8_t)v1;  // rows 8..15
        }

        __syncwarp();
        uint4* dst = g_gate + ((size_t)(bh * 128 + blk)) * 1024 + kt * 64;
        const uint4* src = sGB4 + w * 64;
        dst[lane] = src[lane];
        dst[lane + 32] = src[lane + 32];
    }

    mx0 = fmaxf(mx0, __shfl_xor_sync(0xffffffffu, mx0, 1));
    mx0 = fmaxf(mx0, __shfl_xor_sync(0xffffffffu, mx0, 2));
    mx1 = fmaxf(mx1, __shfl_xor_sync(0xffffffffu, mx1, 1));
    mx1 = fmaxf(mx1, __shfl_xor_sync(0xffffffffu, mx1, 2));
    if ((lane & 3) == 0) {
        int r = lane >> 2;
        g_rowmax[bh * 2048 + blk * 16 + r] = mx0;
        g_rowmax[bh * 2048 + blk * 16 + r + 8] = mx1;
    }
    (void)dummy;
}

// ======== KERNEL B: candidate scan + exact fp32 sparse attention ============
// dyn smem: sO 32768 | list 32768 | sl 512 | sTH 128 | cnt 32
static constexpr int OFF_LIST = 32768;
static constexpr int OFF_SL   = 65536;
static constexpr int OFF_STH  = 66048;
static constexpr int OFF_CNT  = 66176;
static constexpr int SMEM_B_BYTES = 66208;
static constexpr int CAP = 1024;

__global__ void __launch_bounds__(256, 3)
pass2_kernel(const float* __restrict__ gq, const float* __restrict__ gk,
             const float* __restrict__ gv, float* __restrict__ gout)
{
    extern __shared__ uint8_t dynsm[];
    float*    sO   = (float*)dynsm;
    uint32_t* sLIS = (uint32_t*)(dynsm + OFF_LIST);
    float*    sl   = (float*)(dynsm + OFF_SL);
    uint8_t*  sTH  = dynsm + OFF_STH;
    int*      cnt  = (int*)(dynsm + OFF_CNT);

    const int tid = threadIdx.x, w = tid >> 5, lane = tid & 31;
    const uint32_t bh = blockIdx.y;
    const int rowbase = blockIdx.x * 128 + w * 16;   // warp's first global row

    float* sOw = sO + w * 1024;
    uint32_t* listw = sLIS + w * CAP;

    // init
    {
        float4 z = make_float4(0.f, 0.f, 0.f, 0.f);
        for (int i = lane; i < 256; i += 32) ((float4*)sOw)[i] = z;
        if (lane < 16) sl[w * 16 + lane] = 0.f;
        if (lane == 0) cnt[w] = 0;
        if (lane < 16) {
            float mr = g_rowmax[(size_t)bh * 2048 + rowbase + lane];
            int t = min(max((int)floorf(mr - 29.f) - 100, 0), 255);
            sTH[w * 16 + lane] = (uint8_t)t;
        }
        __syncwarp();
    }
    const uint4 thb = *(const uint4*)&sTH[w * 16];

    // ---- scan gate slab: 8 blocks per lane, SIMD byte compare --------------
    const uint4* gslab = g_gate + ((size_t)(bh * 128 + blockIdx.x * 8 + w)) * 1024;
#define PUSH(rr, bb, mm) do { unsigned _m = (mm); while (_m) {                 \
        int _lq = (__ffs(_m) - 1) >> 3; _m &= _m - 1;                          \
        int _idx = atomicAdd(&cnt[w], 1);                                      \
        if (_idx < CAP) listw[_idx] = ((rr) << 12) | ((bb) << 4) | _lq; } } while (0)
#define CHK(word, thw, j, rr, bb) { unsigned _g =                              \
        __vsetgeu4((word), __byte_perm((thw), 0, 0x1111 * (j)));               \
        if (_g) PUSH(rr, bb, _g); }
#pragma unroll 1
    for (int g = 0; g < 8; ++g) {
        int b = g * 32 + lane;
        uint4 W0 = gslab[b * 4 + 0];
        uint4 W1 = gslab[b * 4 + 1];
        uint4 W2 = gslab[b * 4 + 2];
        uint4 W3 = gslab[b * 4 + 3];
        CHK(W0.x, thb.x, 0, 0, b)  CHK(W0.y, thb.x, 1, 1, b)
        CHK(W0.z, thb.x, 2, 2, b)  CHK(W0.w, thb.x, 3, 3, b)
        CHK(W1.x, thb.y, 0, 4, b)  CHK(W1.y, thb.y, 1, 5, b)
        CHK(W1.z, thb.y, 2, 6, b)  CHK(W1.w, thb.y, 3, 7, b)
        CHK(W2.x, thb.z, 0, 8, b)  CHK(W2.y, thb.z, 1, 9, b)
        CHK(W2.z, thb.z, 2, 10, b) CHK(W2.w, thb.z, 3, 11, b)
        CHK(W3.x, thb.w, 0, 12, b) CHK(W3.y, thb.w, 1, 13, b)
        CHK(W3.z, thb.w, 2, 14, b) CHK(W3.w, thb.w, 3, 15, b)
    }
#undef CHK
#undef PUSH
    __syncwarp();
    const int n = min(cnt[w], CAP);

    // ---- process candidates: quad-parallel exact fp32 dot ------------------
    const int qd = lane >> 2, ql = lane & 3;
    const unsigned qmask = 0xFu << (qd * 4);
    const float* qb = gq + (size_t)bh * Sc * Dc;
    const float* kb = gk + (size_t)bh * Sc * Dc;
    const float* vb = gv + (size_t)bh * Sc * Dc;

#pragma unroll 1
    for (int i0 = 0; i0 < n; i0 += 8) {
        int idx = i0 + qd;
        if (idx < n) {
            uint32_t ent = listw[idx];
            int row = ent >> 12, b = (ent >> 4) & 255, lq = ent & 3;
            int gqr = rowbase + row;
            int gkc = b * 8 + lq * 2;
            const float* qr  = qb + (size_t)gqr * Dc + ql * 16;
            const float* kr0 = kb + (size_t)gkc * Dc + ql * 16;
            const float* kr1 = kr0 + Dc;
            float s0 = 0.f, s1 = 0.f;
#pragma unroll
            for (int j = 0; j < 4; ++j) {
                float4 qv = *(const float4*)(qr + 4 * j);
                float4 k0 = *(const float4*)(kr0 + 4 * j);
                float4 k1 = *(const float4*)(kr1 + 4 * j);
                s0 = fmaf(qv.x, k0.x, s0); s0 = fmaf(qv.y, k0.y, s0);
                s0 = fmaf(qv.z, k0.z, s0); s0 = fmaf(qv.w, k0.w, s0);
                s1 = fmaf(qv.x, k1.x, s1); s1 = fmaf(qv.y, k1.y, s1);
                s1 = fmaf(qv.z, k1.z, s1); s1 = fmaf(qv.w, k1.w, s1);
            }
            s0 += __shfl_xor_sync(qmask, s0, 1);
            s0 += __shfl_xor_sync(qmask, s0, 2);
            s1 += __shfl_xor_sync(qmask, s1, 1);
            s1 += __shfl_xor_sync(qmask, s1, 2);
            float mr = g_rowmax[(size_t)bh * 2048 + gqr];
            float c0 = 8.f * s0, c1 = 8.f * s1;
            float e0 = (c0 > mr - 25.f) ? __expf(c0 - mr) : 0.f;
            float e1 = (c1 > mr - 25.f) ? __expf(c1 - mr) : 0.f;
            float p0 = 0.f, p1 = 0.f;
            if (ql == 0) {
                float es = e0 + e1;
                if (es > 0.f) atomicAdd(&sl[w * 16 + row], es);
                if (e0 > 0.f && keep_mask(bh, gqr, gkc))     p0 = e0 * 10.f;
                if (e1 > 0.f && keep_mask(bh, gqr, gkc + 1)) p1 = e1 * 10.f;
            }
            p0 = __shfl_sync(qmask, p0, qd * 4);
            p1 = __shfl_sync(qmask, p1, qd * 4);
            if (p0 > 0.f) {
                const float* vc = vb + (size_t)gkc * Dc + ql * 16;
                float* od = sOw + row * 64 + ql * 16;
#pragma unroll
                for (int j = 0; j < 16; ++j) atomicAdd(od + j, p0 * vc[j]);
            }
            if (p1 > 0.f) {
                const float* vc = vb + (size_t)(gkc + 1) * Dc + ql * 16;
                float* od = sOw + row * 64 + ql * 16;
#pragma unroll
                for (int j = 0; j < 16; ++j) atomicAdd(od + j, p1 * vc[j]);
            }
        }
    }
    __syncwarp();

    // ---- epilogue: normalize + store ---------------------------------------
    for (int i = lane; i < 256; i += 32) {
        int row = i >> 4, c4 = (i & 15) * 4;
        float il = 1.0f / sl[w * 16 + row];
        float4 o4 = *(float4*)&sOw[row * 64 + c4];
        float* dst = gout + ((size_t)bh * Sc + rowbase + row) * Dc + c4;
        *(float4*)dst = make_float4(o4.x * il, o4.y * il, o4.z * il, o4.w * il);
    }
}

extern "C" void kernel_launch(void* const* d_in, const int* in_sizes, int n_in,
                              void* d_out, int out_size)
{
    (void)in_sizes; (void)n_in; (void)out_size;
    const float* q = (const float*)d_in[0];
    const float* k = (const float*)d_in[1];
    const float* v = (const float*)d_in[2];
    float* o = (float*)d_out;

    prepass_kernel<<<8192, 256>>>(q, k);

    dim3 gridA(32, 64);
    pass1_kernel<<<gridA, 128>>>(0);

    cudaFuncSetAttribute(pass2_kernel,
                         cudaFuncAttributeMaxDynamicSharedMemorySize, SMEM_B_BYTES);
    dim3 gridB(16, 64);
    pass2_kernel<<<gridB, 256, SMEM_B_BYTES>>>(q, k, v, o);
}